// round 2
// baseline (speedup 1.0000x reference)
#include <cuda_runtime.h>
#include <cuda_bf16.h>

#define NN   50000
#define NRL  20
#define DEMB 64
#define DHID 128

// Static scratch (no allocations allowed). agg is reused across both layers.
__device__ float g_agg[(long)NN * NRL * DHID];          // 512 MB
__device__ float g_cnt[NN * NRL];                       // 4 MB
__device__ float g_inv[NN * NRL];                       // 4 MB
__device__ float g_h1[(long)NN * DHID];                 // 25.6 MB
__device__ float g_h2[(long)NN * DHID];                 // 25.6 MB
__device__ float g_B1[(NRL * DEMB + DEMB) * DHID];      // 1344 x 128
__device__ float g_B2[(NRL * DHID + DHID) * DHID];      // 2688 x 128

__global__ void zero_kernel(float4* p, long n4) {
    long i = (long)blockIdx.x * blockDim.x + threadIdx.x;
    long stride = (long)gridDim.x * blockDim.x;
    float4 z = make_float4(0.f, 0.f, 0.f, 0.f);
    for (; i < n4; i += stride) p[i] = z;
}

__global__ void count_kernel(const int* __restrict__ dst, const int* __restrict__ et,
                             int E, float* __restrict__ cnt) {
    int i = blockIdx.x * blockDim.x + threadIdx.x;
    if (i < E) atomicAdd(&cnt[dst[i] * NRL + et[i]], 1.0f);
}

__global__ void inv_kernel(const float* __restrict__ cnt, float* __restrict__ inv, int n) {
    int i = blockIdx.x * blockDim.x + threadIdx.x;
    if (i < n) inv[i] = 1.0f / fmaxf(cnt[i], 1.0f);
}

// Each edge handled by DIN/4 threads; one float4 vector-red per thread.
template <int DIN>
__global__ void scatter_kernel(const int* __restrict__ src, const int* __restrict__ dst,
                               const int* __restrict__ et, const float* __restrict__ X,
                               int E, float* __restrict__ agg) {
    const int L = DIN / 4;
    long t = (long)blockIdx.x * blockDim.x + threadIdx.x;
    int e = (int)(t / L);
    int sub = (int)(t % L);
    if (e >= E) return;
    int s = src[e], d = dst[e], r = et[e];
    float4 v = reinterpret_cast<const float4*>(X + (long)s * DIN)[sub];
    float* p = agg + ((long)d * NRL + r) * DIN + sub * 4;
    asm volatile("red.global.add.v4.f32 [%0], {%1,%2,%3,%4};"
                 :: "l"(p), "f"(v.x), "f"(v.y), "f"(v.z), "f"(v.w) : "memory");
}

// Concatenate W [R*din,128] and root [din,128] into one B matrix.
__global__ void prep_kernel(const float* __restrict__ W, const float* __restrict__ root,
                            float* __restrict__ B, int wElems, int rootElems) {
    int total = wElems + rootElems;
    for (int i = blockIdx.x * blockDim.x + threadIdx.x; i < total;
         i += gridDim.x * blockDim.x) {
        B[i] = (i < wElems) ? W[i] : root[i - wElems];
    }
}

// C[NN,128] = A[NN, R*DIN + DIN] @ B[.,128] + bias, optional ReLU.
// A is virtual: k < KA -> agg[n*KA+k] * inv[n*NRL + k/DIN]; else X[n*DIN + k-KA].
// Inner product uses packed fma.rn.f32x2 (FFMA2): 2x fp32 FLOP rate vs scalar FFMA.
template <int DIN>
__global__ void __launch_bounds__(256, 2)
gemm_kernel(const float* __restrict__ Aagg, const float* __restrict__ inv,
            const float* __restrict__ X, const float* __restrict__ B,
            const float* __restrict__ bias, float* __restrict__ C, int relu) {
    const int KA = NRL * DIN;
    const int KT = KA + DIN;
    __shared__ __align__(16) float  As[8][132];
    __shared__ __align__(16) float2 Bs[8][132];   // B values duplicated: (b, b)

    int tid = threadIdx.x;
    int tx = tid & 15;        // output col group (8 cols)
    int ty = tid >> 4;        // output row group (8 rows)
    int bm = blockIdx.x * 128;

    int am = tid >> 1;        // A-load row (0..127)
    int ak = (tid & 1) * 4;   // A-load k offset (0 or 4)
    int bk = tid >> 5;        // B-load k row (0..7)
    int bn = (tid & 31) * 4;  // B-load col

    // acc[i2][j] packs rows {ty*8+2*i2, ty*8+2*i2+1}, col tx*8+j as (lo, hi) fp32.
    unsigned long long acc[4][8];
#pragma unroll
    for (int i = 0; i < 4; i++)
#pragma unroll
        for (int j = 0; j < 8; j++) acc[i][j] = 0ull;

    for (int k0 = 0; k0 < KT; k0 += 8) {
        // Load A tile 128x8 (one float4 per thread), fold 1/cnt scaling.
        int n = bm + am;
        float4 av = make_float4(0.f, 0.f, 0.f, 0.f);
        if (n < NN) {
            int k = k0 + ak;
            if (k < KA) {
                float sc = inv[n * NRL + k / DIN];
                av = *reinterpret_cast<const float4*>(Aagg + (long)n * KA + k);
                av.x *= sc; av.y *= sc; av.z *= sc; av.w *= sc;
            } else {
                av = *reinterpret_cast<const float4*>(X + (long)n * DIN + (k - KA));
            }
        }
        As[ak + 0][am] = av.x;
        As[ak + 1][am] = av.y;
        As[ak + 2][am] = av.z;
        As[ak + 3][am] = av.w;

        // Load B tile 8x128, store duplicated for packed-FMA broadcast operand.
        {
            float4 bv = *reinterpret_cast<const float4*>(B + (long)(k0 + bk) * DHID + bn);
            Bs[bk][bn + 0] = make_float2(bv.x, bv.x);
            Bs[bk][bn + 1] = make_float2(bv.y, bv.y);
            Bs[bk][bn + 2] = make_float2(bv.z, bv.z);
            Bs[bk][bn + 3] = make_float2(bv.w, bv.w);
        }

        __syncthreads();

#pragma unroll
        for (int kk = 0; kk < 8; kk++) {
            unsigned long long a2[4], b2[8];
#pragma unroll
            for (int i = 0; i < 4; i++)
                a2[i] = *reinterpret_cast<const unsigned long long*>(
                    &As[kk][ty * 8 + i * 2]);
#pragma unroll
            for (int j = 0; j < 8; j++)
                b2[j] = *reinterpret_cast<const unsigned long long*>(
                    &Bs[kk][tx * 8 + j]);
#pragma unroll
            for (int i = 0; i < 4; i++)
#pragma unroll
                for (int j = 0; j < 8; j++)
                    asm("fma.rn.f32x2 %0, %1, %2, %0;"
                        : "+l"(acc[i][j]) : "l"(a2[i]), "l"(b2[j]));
        }
        __syncthreads();
    }

#pragma unroll
    for (int i = 0; i < 4; i++) {
#pragma unroll
        for (int j = 0; j < 8; j++) {
            unsigned int lo_u = (unsigned int)(acc[i][j] & 0xffffffffull);
            unsigned int hi_u = (unsigned int)(acc[i][j] >> 32);
            float lo = __uint_as_float(lo_u);
            float hi = __uint_as_float(hi_u);
            int col = tx * 8 + j;
            float bv = bias[col];
            lo += bv; hi += bv;
            if (relu) { lo = fmaxf(lo, 0.f); hi = fmaxf(hi, 0.f); }
            int n0 = bm + ty * 8 + i * 2;
            if (n0 < NN)     C[(long)n0 * DHID + col] = lo;
            if (n0 + 1 < NN) C[(long)(n0 + 1) * DHID + col] = hi;
        }
    }
}

__global__ void decoder_kernel(const int* __restrict__ head, const int* __restrict__ tail,
                               const int* __restrict__ rel, const float* __restrict__ h,
                               const float* __restrict__ rel_emb, float* __restrict__ out,
                               int Bn) {
    int warp = (blockIdx.x * blockDim.x + threadIdx.x) >> 5;
    int lane = threadIdx.x & 31;
    if (warp >= Bn) return;
    const float4* hp = reinterpret_cast<const float4*>(h + (long)head[warp] * DHID);
    const float4* tp = reinterpret_cast<const float4*>(h + (long)tail[warp] * DHID);
    const float4* rp = reinterpret_cast<const float4*>(rel_emb + (long)rel[warp] * DHID);
    float4 a = hp[lane], b = tp[lane], c = rp[lane];
    float s = a.x * b.x * c.x + a.y * b.y * c.y + a.z * b.z * c.z + a.w * b.w * c.w;
#pragma unroll
    for (int o = 16; o; o >>= 1) s += __shfl_xor_sync(0xffffffffu, s, o);
    if (lane == 0) out[warp] = s;
}

extern "C" void kernel_launch(void* const* d_in, const int* in_sizes, int n_in,
                              void* d_out, int out_size) {
    const int*   edge_index = (const int*)d_in[0];
    const int*   edge_type  = (const int*)d_in[1];
    const int*   head       = (const int*)d_in[2];
    const int*   tail       = (const int*)d_in[3];
    const int*   rel        = (const int*)d_in[4];
    const float* node_emb   = (const float*)d_in[5];
    const float* W1         = (const float*)d_in[6];
    const float* root1      = (const float*)d_in[7];
    const float* b1         = (const float*)d_in[8];
    const float* W2         = (const float*)d_in[9];
    const float* root2      = (const float*)d_in[10];
    const float* b2         = (const float*)d_in[11];
    const float* rel_emb    = (const float*)d_in[12];

    int E = in_sizes[0] / 2;
    const int* src = edge_index;
    const int* dst = edge_index + E;

    float *agg, *cnt, *inv, *h1, *h2, *B1, *B2;
    cudaGetSymbolAddress((void**)&agg, g_agg);
    cudaGetSymbolAddress((void**)&cnt, g_cnt);
    cudaGetSymbolAddress((void**)&inv, g_inv);
    cudaGetSymbolAddress((void**)&h1, g_h1);
    cudaGetSymbolAddress((void**)&h2, g_h2);
    cudaGetSymbolAddress((void**)&B1, g_B1);
    cudaGetSymbolAddress((void**)&B2, g_B2);

    const int T = 256;

    // ---- shared prep: counts / inverse counts (graph is identical both layers)
    zero_kernel<<<1024, T>>>((float4*)cnt, (long)NN * NRL / 4);
    count_kernel<<<(E + T - 1) / T, T>>>(dst, edge_type, E, cnt);
    inv_kernel<<<(NN * NRL + T - 1) / T, T>>>(cnt, inv, NN * NRL);

    // ---- layer 1
    zero_kernel<<<4096, T>>>((float4*)agg, (long)NN * NRL * DEMB / 4);
    {
        long threads = (long)E * (DEMB / 4);
        scatter_kernel<DEMB><<<(unsigned)((threads + T - 1) / T), T>>>(
            src, dst, edge_type, node_emb, E, agg);
    }
    prep_kernel<<<512, T>>>(W1, root1, B1, NRL * DEMB * DHID, DEMB * DHID);
    gemm_kernel<DEMB><<<(NN + 127) / 128, T>>>(agg, inv, node_emb, B1, b1, h1, 1);

    // ---- layer 2
    zero_kernel<<<8192, T>>>((float4*)agg, (long)NN * NRL * DHID / 4);
    {
        long threads = (long)E * (DHID / 4);
        scatter_kernel<DHID><<<(unsigned)((threads + T - 1) / T), T>>>(
            src, dst, edge_type, h1, E, agg);
    }
    prep_kernel<<<512, T>>>(W2, root2, B2, NRL * DHID * DHID, DHID * DHID);
    gemm_kernel<DHID><<<(NN + 127) / 128, T>>>(agg, inv, h1, B2, b2, h2, 0);

    // ---- DistMult decoder
    int Bn = in_sizes[2];
    decoder_kernel<<<(Bn * 32 + T - 1) / T, T>>>(head, tail, rel, h2, rel_emb,
                                                 (float*)d_out, Bn);
}

// round 3
// speedup vs baseline: 2.0501x; 2.0501x over previous
#include <cuda_runtime.h>
#include <cuda_bf16.h>

#define NN   50000
#define NRL  20
#define DEMB 64
#define DHID 128

// Static scratch (no allocations allowed). agg is reused across both layers.
__device__ float g_agg[(long)NN * NRL * DHID];          // 512 MB
__device__ float g_cnt[NN * NRL];                       // 4 MB
__device__ float g_inv[NN * NRL];                       // 4 MB
__device__ float g_h1[(long)NN * DHID];                 // 25.6 MB
__device__ float g_h2[(long)NN * DHID];                 // 25.6 MB
__device__ float g_B1[(NRL * DEMB + DEMB) * DHID];      // 1344 x 128
__device__ float g_B2[(NRL * DHID + DHID) * DHID];      // 2688 x 128

__global__ void zero_kernel(float4* p, long n4) {
    long i = (long)blockIdx.x * blockDim.x + threadIdx.x;
    long stride = (long)gridDim.x * blockDim.x;
    float4 z = make_float4(0.f, 0.f, 0.f, 0.f);
    for (; i < n4; i += stride) p[i] = z;
}

__global__ void count_kernel(const int* __restrict__ dst, const int* __restrict__ et,
                             int E, float* __restrict__ cnt) {
    int i = blockIdx.x * blockDim.x + threadIdx.x;
    if (i < E) atomicAdd(&cnt[dst[i] * NRL + et[i]], 1.0f);
}

__global__ void inv_kernel(const float* __restrict__ cnt, float* __restrict__ inv, int n) {
    int i = blockIdx.x * blockDim.x + threadIdx.x;
    if (i < n) inv[i] = 1.0f / fmaxf(cnt[i], 1.0f);
}

// Each edge handled by DIN/4 threads; one float4 vector-red per thread.
template <int DIN>
__global__ void scatter_kernel(const int* __restrict__ src, const int* __restrict__ dst,
                               const int* __restrict__ et, const float* __restrict__ X,
                               int E, float* __restrict__ agg) {
    const int L = DIN / 4;
    long t = (long)blockIdx.x * blockDim.x + threadIdx.x;
    int e = (int)(t / L);
    int sub = (int)(t % L);
    if (e >= E) return;
    int s = src[e], d = dst[e], r = et[e];
    float4 v = reinterpret_cast<const float4*>(X + (long)s * DIN)[sub];
    float* p = agg + ((long)d * NRL + r) * DIN + sub * 4;
    asm volatile("red.global.add.v4.f32 [%0], {%1,%2,%3,%4};"
                 :: "l"(p), "f"(v.x), "f"(v.y), "f"(v.z), "f"(v.w) : "memory");
}

// Concatenate W [R*din,128] and root [din,128] into one B matrix.
__global__ void prep_kernel(const float* __restrict__ W, const float* __restrict__ root,
                            float* __restrict__ B, int wElems, int rootElems) {
    int total = wElems + rootElems;
    for (int i = blockIdx.x * blockDim.x + threadIdx.x; i < total;
         i += gridDim.x * blockDim.x) {
        B[i] = (i < wElems) ? W[i] : root[i - wElems];
    }
}

__device__ __forceinline__ unsigned pack2(__nv_bfloat16 lo, __nv_bfloat16 hi) {
    unsigned short a = *reinterpret_cast<unsigned short*>(&lo);
    unsigned short b = *reinterpret_cast<unsigned short*>(&hi);
    return (unsigned)a | ((unsigned)b << 16);
}

#define MMA_BF16(ACC, A, B0, B1)                                              \
    asm volatile(                                                             \
        "mma.sync.aligned.m16n8k16.row.col.f32.bf16.bf16.f32 "                \
        "{%0,%1,%2,%3}, {%4,%5,%6,%7}, {%8,%9}, {%0,%1,%2,%3};"               \
        : "+f"((ACC)[0]), "+f"((ACC)[1]), "+f"((ACC)[2]), "+f"((ACC)[3])      \
        : "r"((A)[0]), "r"((A)[1]), "r"((A)[2]), "r"((A)[3]),                 \
          "r"(B0), "r"(B1))

// C[NN,128] = A[NN, R*DIN + DIN] @ B[.,128] + bias, optional ReLU.
// A is virtual: k < KA -> agg[n*KA+k] * inv[n*NRL + k/DIN]; else X[n*DIN + k-KA].
// Tensor-core bf16 split emulation: A = Ah+Al, B = Bh+Bl (bf16 each),
// acc += Ah*Bh + Ah*Bl + Al*Bh  (fp32 accumulate)  -> ~1e-5 rel error.
template <int DIN>
__global__ void __launch_bounds__(256, 1)
gemm_mma_kernel(const float* __restrict__ Aagg, const float* __restrict__ inv,
                const float* __restrict__ X, const float* __restrict__ B,
                const float* __restrict__ bias, float* __restrict__ C, int relu) {
    const int KA = NRL * DIN;
    const int KT = KA + DIN;
    const int BK = 32;

    __shared__ __align__(16) __nv_bfloat16 Ah[128][40];   // pad 8
    __shared__ __align__(16) __nv_bfloat16 Al[128][40];
    __shared__ __align__(16) __nv_bfloat16 Bh[32][136];   // pad 8
    __shared__ __align__(16) __nv_bfloat16 Bl[32][136];

    int tid = threadIdx.x;
    int wid = tid >> 5;
    int lane = tid & 31;
    int wm = wid & 3;        // warp row tile 0..3 (32 rows each)
    int wn = wid >> 2;       // warp col tile 0..1 (64 cols each)
    int bm = blockIdx.x * 128;

    int lg = lane >> 2;      // lane group 0..7
    int lq = lane & 3;       // quad lane 0..3

    float acc[2][8][4];
#pragma unroll
    for (int ma = 0; ma < 2; ma++)
#pragma unroll
        for (int na = 0; na < 8; na++)
#pragma unroll
            for (int r = 0; r < 4; r++) acc[ma][na][r] = 0.f;

    for (int k0 = 0; k0 < KT; k0 += BK) {
        // ---- load A tile (128 x 32 fp32), split into hi/lo bf16 planes
#pragma unroll
        for (int p = 0; p < 4; p++) {
            int idx = p * 256 + tid;
            int r = idx >> 3;
            int c4 = (idx & 7) * 4;
            int n = bm + r;
            float4 av = make_float4(0.f, 0.f, 0.f, 0.f);
            if (n < NN) {
                int k = k0 + c4;
                if (k < KA) {
                    float sc = inv[n * NRL + k / DIN];
                    av = *reinterpret_cast<const float4*>(Aagg + (long)n * KA + k);
                    av.x *= sc; av.y *= sc; av.z *= sc; av.w *= sc;
                } else {
                    av = *reinterpret_cast<const float4*>(X + (long)n * DIN + (k - KA));
                }
            }
            __nv_bfloat16 h0 = __float2bfloat16(av.x);
            __nv_bfloat16 h1 = __float2bfloat16(av.y);
            __nv_bfloat16 h2 = __float2bfloat16(av.z);
            __nv_bfloat16 h3 = __float2bfloat16(av.w);
            __nv_bfloat16 l0 = __float2bfloat16(av.x - __bfloat162float(h0));
            __nv_bfloat16 l1 = __float2bfloat16(av.y - __bfloat162float(h1));
            __nv_bfloat16 l2 = __float2bfloat16(av.z - __bfloat162float(h2));
            __nv_bfloat16 l3 = __float2bfloat16(av.w - __bfloat162float(h3));
            *reinterpret_cast<uint2*>(&Ah[r][c4]) = make_uint2(pack2(h0, h1), pack2(h2, h3));
            *reinterpret_cast<uint2*>(&Al[r][c4]) = make_uint2(pack2(l0, l1), pack2(l2, l3));
        }
        // ---- load B tile (32 x 128 fp32), split into hi/lo bf16 planes
#pragma unroll
        for (int p = 0; p < 4; p++) {
            int idx = p * 256 + tid;
            int k = idx >> 5;
            int n4 = (idx & 31) * 4;
            float4 bv = *reinterpret_cast<const float4*>(B + (long)(k0 + k) * DHID + n4);
            __nv_bfloat16 h0 = __float2bfloat16(bv.x);
            __nv_bfloat16 h1 = __float2bfloat16(bv.y);
            __nv_bfloat16 h2 = __float2bfloat16(bv.z);
            __nv_bfloat16 h3 = __float2bfloat16(bv.w);
            __nv_bfloat16 l0 = __float2bfloat16(bv.x - __bfloat162float(h0));
            __nv_bfloat16 l1 = __float2bfloat16(bv.y - __bfloat162float(h1));
            __nv_bfloat16 l2 = __float2bfloat16(bv.z - __bfloat162float(h2));
            __nv_bfloat16 l3 = __float2bfloat16(bv.w - __bfloat162float(h3));
            *reinterpret_cast<uint2*>(&Bh[k][n4]) = make_uint2(pack2(h0, h1), pack2(h2, h3));
            *reinterpret_cast<uint2*>(&Bl[k][n4]) = make_uint2(pack2(l0, l1), pack2(l2, l3));
        }
        __syncthreads();

#pragma unroll
        for (int ks = 0; ks < BK; ks += 16) {
            // A fragments for both m-atoms, both planes
            unsigned ah[2][4], al[2][4];
#pragma unroll
            for (int ma = 0; ma < 2; ma++) {
                int r0 = wm * 32 + ma * 16 + lg;
                int kc = ks + lq * 2;
                ah[ma][0] = *reinterpret_cast<unsigned*>(&Ah[r0][kc]);
                ah[ma][1] = *reinterpret_cast<unsigned*>(&Ah[r0 + 8][kc]);
                ah[ma][2] = *reinterpret_cast<unsigned*>(&Ah[r0][kc + 8]);
                ah[ma][3] = *reinterpret_cast<unsigned*>(&Ah[r0 + 8][kc + 8]);
                al[ma][0] = *reinterpret_cast<unsigned*>(&Al[r0][kc]);
                al[ma][1] = *reinterpret_cast<unsigned*>(&Al[r0 + 8][kc]);
                al[ma][2] = *reinterpret_cast<unsigned*>(&Al[r0][kc + 8]);
                al[ma][3] = *reinterpret_cast<unsigned*>(&Al[r0 + 8][kc + 8]);
            }
            // B fragments for all 8 n-atoms, both planes
            unsigned bh0[8], bh1[8], bl0[8], bl1[8];
#pragma unroll
            for (int na = 0; na < 8; na++) {
                int nb = wn * 64 + na * 8 + lg;
                int kl = ks + lq * 2;
                bh0[na] = pack2(Bh[kl][nb], Bh[kl + 1][nb]);
                bh1[na] = pack2(Bh[kl + 8][nb], Bh[kl + 9][nb]);
                bl0[na] = pack2(Bl[kl][nb], Bl[kl + 1][nb]);
                bl1[na] = pack2(Bl[kl + 8][nb], Bl[kl + 9][nb]);
            }
            // 3 passes, dependency chains broken by na/ma interleave
#pragma unroll
            for (int na = 0; na < 8; na++)
#pragma unroll
                for (int ma = 0; ma < 2; ma++)
                    MMA_BF16(acc[ma][na], ah[ma], bh0[na], bh1[na]);
#pragma unroll
            for (int na = 0; na < 8; na++)
#pragma unroll
                for (int ma = 0; ma < 2; ma++)
                    MMA_BF16(acc[ma][na], ah[ma], bl0[na], bl1[na]);
#pragma unroll
            for (int na = 0; na < 8; na++)
#pragma unroll
                for (int ma = 0; ma < 2; ma++)
                    MMA_BF16(acc[ma][na], al[ma], bh0[na], bh1[na]);
        }
        __syncthreads();
    }

    // ---- epilogue: bias (+ReLU), store
#pragma unroll
    for (int ma = 0; ma < 2; ma++) {
#pragma unroll
        for (int na = 0; na < 8; na++) {
            int col = wn * 64 + na * 8 + lq * 2;
            float2 bv = *reinterpret_cast<const float2*>(&bias[col]);
            float v0 = acc[ma][na][0] + bv.x;
            float v1 = acc[ma][na][1] + bv.y;
            float v2 = acc[ma][na][2] + bv.x;
            float v3 = acc[ma][na][3] + bv.y;
            if (relu) {
                v0 = fmaxf(v0, 0.f); v1 = fmaxf(v1, 0.f);
                v2 = fmaxf(v2, 0.f); v3 = fmaxf(v3, 0.f);
            }
            int row0 = bm + wm * 32 + ma * 16 + lg;
            int row1 = row0 + 8;
            if (row0 < NN)
                *reinterpret_cast<float2*>(&C[(long)row0 * DHID + col]) = make_float2(v0, v1);
            if (row1 < NN)
                *reinterpret_cast<float2*>(&C[(long)row1 * DHID + col]) = make_float2(v2, v3);
        }
    }
}

__global__ void decoder_kernel(const int* __restrict__ head, const int* __restrict__ tail,
                               const int* __restrict__ rel, const float* __restrict__ h,
                               const float* __restrict__ rel_emb, float* __restrict__ out,
                               int Bn) {
    int warp = (blockIdx.x * blockDim.x + threadIdx.x) >> 5;
    int lane = threadIdx.x & 31;
    if (warp >= Bn) return;
    const float4* hp = reinterpret_cast<const float4*>(h + (long)head[warp] * DHID);
    const float4* tp = reinterpret_cast<const float4*>(h + (long)tail[warp] * DHID);
    const float4* rp = reinterpret_cast<const float4*>(rel_emb + (long)rel[warp] * DHID);
    float4 a = hp[lane], b = tp[lane], c = rp[lane];
    float s = a.x * b.x * c.x + a.y * b.y * c.y + a.z * b.z * c.z + a.w * b.w * c.w;
#pragma unroll
    for (int o = 16; o; o >>= 1) s += __shfl_xor_sync(0xffffffffu, s, o);
    if (lane == 0) out[warp] = s;
}

extern "C" void kernel_launch(void* const* d_in, const int* in_sizes, int n_in,
                              void* d_out, int out_size) {
    const int*   edge_index = (const int*)d_in[0];
    const int*   edge_type  = (const int*)d_in[1];
    const int*   head       = (const int*)d_in[2];
    const int*   tail       = (const int*)d_in[3];
    const int*   rel        = (const int*)d_in[4];
    const float* node_emb   = (const float*)d_in[5];
    const float* W1         = (const float*)d_in[6];
    const float* root1      = (const float*)d_in[7];
    const float* b1         = (const float*)d_in[8];
    const float* W2         = (const float*)d_in[9];
    const float* root2      = (const float*)d_in[10];
    const float* b2         = (const float*)d_in[11];
    const float* rel_emb    = (const float*)d_in[12];

    int E = in_sizes[0] / 2;
    const int* src = edge_index;
    const int* dst = edge_index + E;

    float *agg, *cnt, *inv, *h1, *h2, *B1, *B2;
    cudaGetSymbolAddress((void**)&agg, g_agg);
    cudaGetSymbolAddress((void**)&cnt, g_cnt);
    cudaGetSymbolAddress((void**)&inv, g_inv);
    cudaGetSymbolAddress((void**)&h1, g_h1);
    cudaGetSymbolAddress((void**)&h2, g_h2);
    cudaGetSymbolAddress((void**)&B1, g_B1);
    cudaGetSymbolAddress((void**)&B2, g_B2);

    const int T = 256;

    // ---- shared prep: counts / inverse counts (graph is identical both layers)
    zero_kernel<<<1024, T>>>((float4*)cnt, (long)NN * NRL / 4);
    count_kernel<<<(E + T - 1) / T, T>>>(dst, edge_type, E, cnt);
    inv_kernel<<<(NN * NRL + T - 1) / T, T>>>(cnt, inv, NN * NRL);

    // ---- layer 1
    zero_kernel<<<4096, T>>>((float4*)agg, (long)NN * NRL * DEMB / 4);
    {
        long threads = (long)E * (DEMB / 4);
        scatter_kernel<DEMB><<<(unsigned)((threads + T - 1) / T), T>>>(
            src, dst, edge_type, node_emb, E, agg);
    }
    prep_kernel<<<512, T>>>(W1, root1, B1, NRL * DEMB * DHID, DEMB * DHID);
    gemm_mma_kernel<DEMB><<<(NN + 127) / 128, T>>>(agg, inv, node_emb, B1, b1, h1, 1);

    // ---- layer 2
    zero_kernel<<<8192, T>>>((float4*)agg, (long)NN * NRL * DHID / 4);
    {
        long threads = (long)E * (DHID / 4);
        scatter_kernel<DHID><<<(unsigned)((threads + T - 1) / T), T>>>(
            src, dst, edge_type, h1, E, agg);
    }
    prep_kernel<<<512, T>>>(W2, root2, B2, NRL * DHID * DHID, DHID * DHID);
    gemm_mma_kernel<DHID><<<(NN + 127) / 128, T>>>(agg, inv, h1, B2, b2, h2, 0);

    // ---- DistMult decoder
    int Bn = in_sizes[2];
    decoder_kernel<<<(Bn * 32 + T - 1) / T, T>>>(head, tail, rel, h2, rel_emb,
                                                 (float*)d_out, Bn);
}